// round 2
// baseline (speedup 1.0000x reference)
#include <cuda_runtime.h>
#include <math.h>

#define BB 4
#define SS 4096
#define DD 128
#define HH 256
#define NTOK (BB*SS)

// Scratch (device globals: allocation-free rule)
__device__ float g_q[NTOK*DD];      // 8 MB
__device__ float g_k[NTOK*DD];      // 8 MB
__device__ float g_v[NTOK*HH];      // 16 MB
__device__ float g_gate[NTOK*HH];   // 16 MB

__device__ __forceinline__ float silu_f(float x) {
    return x / (1.0f + expf(-x));
}

// ---------------------------------------------------------------------------
// Kernel 1: per-token preproc.
// rope(query) -> layernorm -> qk = silu(n@Wqk+b) -> q,k (gamma/beta)
//                             gate = silu(n@Wg+b), v = silu(value@Wg+b)
// 16 tokens per block, 256 threads. Warp w handles tokens 2w, 2w+1 in phase A.
// ---------------------------------------------------------------------------
__global__ void __launch_bounds__(256) k_pre(
    const float* __restrict__ q_in, const float* __restrict__ v_in,
    const float* __restrict__ ln_g, const float* __restrict__ ln_b,
    const float* __restrict__ Wg,   const float* __restrict__ bg,
    const float* __restrict__ Wqk,  const float* __restrict__ bqk,
    const float* __restrict__ gam,  const float* __restrict__ bet)
{
    __shared__ float nrm[16][128];
    __shared__ float val[16][128];

    const int t = threadIdx.x;
    const int w = t >> 5, l = t & 31;
    const long g0 = (long)blockIdx.x * 16;

    // ---- Phase A: rope + layernorm (one warp per token, 2 tokens/warp) ----
    for (int u = 0; u < 2; ++u) {
        const int tok = w * 2 + u;
        const long g = g0 + tok;
        const int s = (int)(g & (SS - 1));

        float4 x = reinterpret_cast<const float4*>(q_in)[g * 32 + l];

        if (l < 8) {  // dims 4l..4l+3 < 32 -> rotary. pair indices i0=2l, i1=2l+1
            const float f0 = powf(10000.0f, -(float)(4 * l)     / 32.0f);
            const float f1 = powf(10000.0f, -(float)(4 * l + 2) / 32.0f);
            float s0, c0, s1, c1;
            sincosf((float)s * f0, &s0, &c0);
            sincosf((float)s * f1, &s1, &c1);
            float a = x.x, b2 = x.y;
            x.x = a * c0 - b2 * s0;  x.y = b2 * c0 + a * s0;
            a = x.z;  b2 = x.w;
            x.z = a * c1 - b2 * s1;  x.w = b2 * c1 + a * s1;
        }

        float sum = x.x + x.y + x.z + x.w;
        float sq  = x.x*x.x + x.y*x.y + x.z*x.z + x.w*x.w;
        #pragma unroll
        for (int o = 16; o > 0; o >>= 1) {
            sum += __shfl_xor_sync(0xffffffffu, sum, o);
            sq  += __shfl_xor_sync(0xffffffffu, sq,  o);
        }
        const float mu  = sum * (1.0f / 128.0f);
        const float var = sq  * (1.0f / 128.0f) - mu * mu;
        const float rs  = rsqrtf(var + 1e-5f);

        const int d0 = 4 * l;
        float4 n;
        n.x = (x.x - mu) * rs * ln_g[d0 + 0] + ln_b[d0 + 0];
        n.y = (x.y - mu) * rs * ln_g[d0 + 1] + ln_b[d0 + 1];
        n.z = (x.z - mu) * rs * ln_g[d0 + 2] + ln_b[d0 + 2];
        n.w = (x.w - mu) * rs * ln_g[d0 + 3] + ln_b[d0 + 3];
        reinterpret_cast<float4*>(&nrm[tok][0])[l] = n;
        reinterpret_cast<float4*>(&val[tok][0])[l] =
            reinterpret_cast<const float4*>(v_in)[g * 32 + l];
    }
    __syncthreads();

    // ---- Phase B1: qk -> q,k. threads 0..127 do even tokens, 128..255 odd ----
    {
        const int c = t & 127, half = t >> 7;
        float acc[8];
        #pragma unroll
        for (int j = 0; j < 8; ++j) acc[j] = 0.0f;
        for (int k = 0; k < 128; ++k) {
            const float wv = Wqk[k * 128 + c];
            #pragma unroll
            for (int j = 0; j < 8; ++j)
                acc[j] += nrm[2 * j + half][k] * wv;   // smem broadcast
        }
        const float gz0 = gam[c], gz1 = gam[128 + c];
        const float bz0 = bet[c], bz1 = bet[128 + c];
        const float bb = bqk[c];
        #pragma unroll
        for (int j = 0; j < 8; ++j) {
            const long g = g0 + 2 * j + half;
            const float sl = silu_f(acc[j] + bb);
            g_q[g * 128 + c] = sl * gz0 + bz0;
            g_k[g * 128 + c] = sl * gz1 + bz1;
        }
    }

    // ---- Phase B2: gate and v (all 256 threads, one H-column each) ----
    {
        const int c = t;
        float ag[16], av[16];
        #pragma unroll
        for (int j = 0; j < 16; ++j) { ag[j] = 0.0f; av[j] = 0.0f; }
        for (int k = 0; k < 128; ++k) {
            const float wv = Wg[k * 256 + c];
            #pragma unroll
            for (int j = 0; j < 16; ++j) {
                ag[j] += nrm[j][k] * wv;
                av[j] += val[j][k] * wv;
            }
        }
        const float bb = bg[c];
        #pragma unroll
        for (int j = 0; j < 16; ++j) {
            const long g = g0 + j;
            g_gate[g * 256 + c] = silu_f(ag[j] + bb);
            g_v[g * 256 + c]    = silu_f(av[j] + bb);
        }
    }
}

// ---------------------------------------------------------------------------
// Kernel 2: fused attention.
// Per block: 64 query rows of one batch. Loop over 64-row K/V tiles:
//   sim = q.k^T/S  -> attn = relu^2 -> write att_map tile + smem
//   o += attn @ v   (o stays in registers, 64x256 across 256 threads)
// Epilogue in-block: out = (o*gate) @ W_out + b_out.
// smem: qs/ks stride 129 (conflict-free), attn stride 68 (16B-aligned rows).
// ---------------------------------------------------------------------------
#define QK_STRIDE 129
#define AT_STRIDE 68
#define SMEM_BYTES ((2*64*QK_STRIDE + 64*AT_STRIDE + 64*256) * 4)

__global__ void __launch_bounds__(256, 1) k_attn(
    const float* __restrict__ Wout, const float* __restrict__ bout,
    float* __restrict__ out, float* __restrict__ att)
{
    extern __shared__ float sm[];
    float* qs = sm;                                  // 64 x 129
    float* ks = sm + 64 * QK_STRIDE;                 // 64 x 129
    float* as = sm + 2 * 64 * QK_STRIDE;             // 64 x 68
    float* vs = as + 64 * AT_STRIDE;                 // 64 x 256
    float4* vs4 = reinterpret_cast<float4*>(vs);

    const int t  = threadIdx.x;
    const int b  = blockIdx.y;
    const int i0 = blockIdx.x * 64;
    const long tbase = (long)b * SS;
    float* attb = att + (size_t)b * SS * SS;

    // load q tile (global float4 -> padded smem scalars)
    for (int i = t; i < 64 * 32; i += 256) {
        const int r = i >> 5, c4 = i & 31;
        float4 v = reinterpret_cast<const float4*>(g_q)[(tbase + i0 + r) * 32 + c4];
        float* dst = qs + r * QK_STRIDE + c4 * 4;
        dst[0] = v.x; dst[1] = v.y; dst[2] = v.z; dst[3] = v.w;
    }

    float o[8][8];
    #pragma unroll
    for (int a = 0; a < 8; ++a)
        #pragma unroll
        for (int c = 0; c < 8; ++c) o[a][c] = 0.0f;

    const int ty = t >> 4, tx = t & 15;       // sim: 16x16 threads, 4x4 each
    const int w  = t >> 5, lane = t & 31;     // pv:  8x32  threads, 8x8 each
    const float invS = 1.0f / (float)SS;

    for (int j0 = 0; j0 < SS; j0 += 64) {
        __syncthreads();  // also protects qs on first iter, ks/vs reuse after

        for (int i = t; i < 64 * 32; i += 256) {
            const int r = i >> 5, c4 = i & 31;
            float4 v = reinterpret_cast<const float4*>(g_k)[(tbase + j0 + r) * 32 + c4];
            float* dst = ks + r * QK_STRIDE + c4 * 4;
            dst[0] = v.x; dst[1] = v.y; dst[2] = v.z; dst[3] = v.w;
        }
        for (int i = t; i < 64 * 64; i += 256)
            vs4[i] = reinterpret_cast<const float4*>(g_v)[(tbase + j0) * 64 + i];
        __syncthreads();

        // ---- sim: 4x4 per thread ----
        float acc[4][4];
        #pragma unroll
        for (int r = 0; r < 4; ++r)
            #pragma unroll
            for (int c = 0; c < 4; ++c) acc[r][c] = 0.0f;

        const float* qp = qs + (ty * 4) * QK_STRIDE;
        const float* kp = ks + (tx * 4) * QK_STRIDE;
        #pragma unroll 4
        for (int d = 0; d < 128; ++d) {
            const float q0 = qp[d], q1 = qp[QK_STRIDE + d],
                        q2 = qp[2 * QK_STRIDE + d], q3 = qp[3 * QK_STRIDE + d];
            const float k0 = kp[d], k1 = kp[QK_STRIDE + d],
                        k2 = kp[2 * QK_STRIDE + d], k3 = kp[3 * QK_STRIDE + d];
            acc[0][0] += q0 * k0; acc[0][1] += q0 * k1; acc[0][2] += q0 * k2; acc[0][3] += q0 * k3;
            acc[1][0] += q1 * k0; acc[1][1] += q1 * k1; acc[1][2] += q1 * k2; acc[1][3] += q1 * k3;
            acc[2][0] += q2 * k0; acc[2][1] += q2 * k1; acc[2][2] += q2 * k2; acc[2][3] += q2 * k3;
            acc[3][0] += q3 * k0; acc[3][1] += q3 * k1; acc[3][2] += q3 * k2; acc[3][3] += q3 * k3;
        }

        // ---- relu^2, write att_map + attn smem ----
        #pragma unroll
        for (int r = 0; r < 4; ++r) {
            float4 av;
            float x;
            x = fmaxf(acc[r][0], 0.0f) * invS; av.x = x * x;
            x = fmaxf(acc[r][1], 0.0f) * invS; av.y = x * x;
            x = fmaxf(acc[r][2], 0.0f) * invS; av.z = x * x;
            x = fmaxf(acc[r][3], 0.0f) * invS; av.w = x * x;
            *reinterpret_cast<float4*>(as + (ty * 4 + r) * AT_STRIDE + tx * 4) = av;
            reinterpret_cast<float4*>(attb)[(size_t)(i0 + ty * 4 + r) * (SS / 4)
                                            + (j0 >> 2) + tx] = av;
        }
        __syncthreads();

        // ---- PV: o[8x8] += attn @ v ----
        #pragma unroll 2
        for (int jb = 0; jb < 64; ++jb) {
            const float4 v0 = vs4[jb * 64 + lane * 2];
            const float4 v1 = vs4[jb * 64 + lane * 2 + 1];
            #pragma unroll
            for (int rr = 0; rr < 8; ++rr) {
                const float a = as[(w * 8 + rr) * AT_STRIDE + jb];  // broadcast
                o[rr][0] += a * v0.x; o[rr][1] += a * v0.y;
                o[rr][2] += a * v0.z; o[rr][3] += a * v0.w;
                o[rr][4] += a * v1.x; o[rr][5] += a * v1.y;
                o[rr][6] += a * v1.z; o[rr][7] += a * v1.w;
            }
        }
    }

    // ---- epilogue: og = o*gate into smem (reuse vs), then @ W_out + b ----
    __syncthreads();
    #pragma unroll
    for (int rr = 0; rr < 8; ++rr) {
        const long g = tbase + i0 + w * 8 + rr;
        const float4 g0v = reinterpret_cast<const float4*>(g_gate)[g * 64 + lane * 2];
        const float4 g1v = reinterpret_cast<const float4*>(g_gate)[g * 64 + lane * 2 + 1];
        float4 a, bq;
        a.x  = o[rr][0] * g0v.x; a.y  = o[rr][1] * g0v.y;
        a.z  = o[rr][2] * g0v.z; a.w  = o[rr][3] * g0v.w;
        bq.x = o[rr][4] * g1v.x; bq.y = o[rr][5] * g1v.y;
        bq.z = o[rr][6] * g1v.z; bq.w = o[rr][7] * g1v.w;
        vs4[(w * 8 + rr) * 64 + lane * 2]     = a;
        vs4[(w * 8 + rr) * 64 + lane * 2 + 1] = bq;
    }
    __syncthreads();

    {
        const int c = t & 127, r0 = t >> 7;
        float acc2[32];
        #pragma unroll
        for (int i = 0; i < 32; ++i) acc2[i] = 0.0f;
        for (int h = 0; h < 256; ++h) {
            const float wv = Wout[h * 128 + c];
            #pragma unroll
            for (int i = 0; i < 32; ++i)
                acc2[i] += vs[(r0 + 2 * i) * 256 + h] * wv;  // broadcast
        }
        const float bb = bout[c];
        #pragma unroll
        for (int i = 0; i < 32; ++i)
            out[(tbase + i0 + r0 + 2 * i) * 128 + c] = acc2[i] + bb;
    }
}

// ---------------------------------------------------------------------------
extern "C" void kernel_launch(void* const* d_in, const int* in_sizes, int n_in,
                              void* d_out, int out_size)
{
    const float* query = (const float*)d_in[0];
    // d_in[1] = key: unused by the reference
    const float* value = (const float*)d_in[2];
    const float* ln_g  = (const float*)d_in[3];
    const float* ln_b  = (const float*)d_in[4];
    const float* Wg    = (const float*)d_in[5];
    const float* bg    = (const float*)d_in[6];
    const float* Wqk   = (const float*)d_in[7];
    const float* bqk   = (const float*)d_in[8];
    const float* gam   = (const float*)d_in[9];
    const float* bet   = (const float*)d_in[10];
    const float* Wout  = (const float*)d_in[11];
    const float* bout  = (const float*)d_in[12];

    float* out = (float*)d_out;                       // [B,S,D] first
    float* att = out + (size_t)BB * SS * DD;          // then [B,S,S]

    cudaFuncSetAttribute(k_attn, cudaFuncAttributeMaxDynamicSharedMemorySize,
                         SMEM_BYTES);

    k_pre<<<NTOK / 16, 256>>>(query, value, ln_g, ln_b, Wg, bg, Wqk, bqk, gam, bet);

    dim3 g2(SS / 64, BB);
    k_attn<<<g2, 256, SMEM_BYTES>>>(Wout, bout, out, att);
}

// round 3
// speedup vs baseline: 1.0591x; 1.0591x over previous
#include <cuda_runtime.h>
#include <math.h>

#define BB 4
#define SS 4096
#define DD 128
#define HH 256
#define NTOK (BB*SS)

// Scratch (device globals: allocation-free rule)
__device__ float g_q[NTOK*DD];      // 8 MB
__device__ float g_k[NTOK*DD];      // 8 MB
__device__ float g_v[NTOK*HH];      // 16 MB
__device__ float g_gate[NTOK*HH];   // 16 MB

__device__ __forceinline__ float silu_f(float x) {
    return x / (1.0f + expf(-x));
}

// ---------------------------------------------------------------------------
// Kernel 1: per-token preproc (unchanged from passing R1 kernel).
// ---------------------------------------------------------------------------
__global__ void __launch_bounds__(256) k_pre(
    const float* __restrict__ q_in, const float* __restrict__ v_in,
    const float* __restrict__ ln_g, const float* __restrict__ ln_b,
    const float* __restrict__ Wg,   const float* __restrict__ bg,
    const float* __restrict__ Wqk,  const float* __restrict__ bqk,
    const float* __restrict__ gam,  const float* __restrict__ bet)
{
    __shared__ float nrm[16][128];
    __shared__ float val[16][128];

    const int t = threadIdx.x;
    const int w = t >> 5, l = t & 31;
    const long g0 = (long)blockIdx.x * 16;

    for (int u = 0; u < 2; ++u) {
        const int tok = w * 2 + u;
        const long g = g0 + tok;
        const int s = (int)(g & (SS - 1));

        float4 x = reinterpret_cast<const float4*>(q_in)[g * 32 + l];

        if (l < 8) {
            const float f0 = powf(10000.0f, -(float)(4 * l)     / 32.0f);
            const float f1 = powf(10000.0f, -(float)(4 * l + 2) / 32.0f);
            float s0, c0, s1, c1;
            sincosf((float)s * f0, &s0, &c0);
            sincosf((float)s * f1, &s1, &c1);
            float a = x.x, b2 = x.y;
            x.x = a * c0 - b2 * s0;  x.y = b2 * c0 + a * s0;
            a = x.z;  b2 = x.w;
            x.z = a * c1 - b2 * s1;  x.w = b2 * c1 + a * s1;
        }

        float sum = x.x + x.y + x.z + x.w;
        float sq  = x.x*x.x + x.y*x.y + x.z*x.z + x.w*x.w;
        #pragma unroll
        for (int o = 16; o > 0; o >>= 1) {
            sum += __shfl_xor_sync(0xffffffffu, sum, o);
            sq  += __shfl_xor_sync(0xffffffffu, sq,  o);
        }
        const float mu  = sum * (1.0f / 128.0f);
        const float var = sq  * (1.0f / 128.0f) - mu * mu;
        const float rs  = rsqrtf(var + 1e-5f);

        const int d0 = 4 * l;
        float4 n;
        n.x = (x.x - mu) * rs * ln_g[d0 + 0] + ln_b[d0 + 0];
        n.y = (x.y - mu) * rs * ln_g[d0 + 1] + ln_b[d0 + 1];
        n.z = (x.z - mu) * rs * ln_g[d0 + 2] + ln_b[d0 + 2];
        n.w = (x.w - mu) * rs * ln_g[d0 + 3] + ln_b[d0 + 3];
        reinterpret_cast<float4*>(&nrm[tok][0])[l] = n;
        reinterpret_cast<float4*>(&val[tok][0])[l] =
            reinterpret_cast<const float4*>(v_in)[g * 32 + l];
    }
    __syncthreads();

    {   // qk -> q,k
        const int c = t & 127, half = t >> 7;
        float acc[8];
        #pragma unroll
        for (int j = 0; j < 8; ++j) acc[j] = 0.0f;
        for (int k = 0; k < 128; ++k) {
            const float wv = Wqk[k * 128 + c];
            #pragma unroll
            for (int j = 0; j < 8; ++j)
                acc[j] += nrm[2 * j + half][k] * wv;
        }
        const float gz0 = gam[c], gz1 = gam[128 + c];
        const float bz0 = bet[c], bz1 = bet[128 + c];
        const float bb = bqk[c];
        #pragma unroll
        for (int j = 0; j < 8; ++j) {
            const long g = g0 + 2 * j + half;
            const float sl = silu_f(acc[j] + bb);
            g_q[g * 128 + c] = sl * gz0 + bz0;
            g_k[g * 128 + c] = sl * gz1 + bz1;
        }
    }

    {   // gate, v
        const int c = t;
        float ag[16], av[16];
        #pragma unroll
        for (int j = 0; j < 16; ++j) { ag[j] = 0.0f; av[j] = 0.0f; }
        for (int k = 0; k < 128; ++k) {
            const float wv = Wg[k * 256 + c];
            #pragma unroll
            for (int j = 0; j < 16; ++j) {
                ag[j] += nrm[j][k] * wv;
                av[j] += val[j][k] * wv;
            }
        }
        const float bb = bg[c];
        #pragma unroll
        for (int j = 0; j < 16; ++j) {
            const long g = g0 + j;
            g_gate[g * 256 + c] = silu_f(ag[j] + bb);
            g_v[g * 256 + c]    = silu_f(av[j] + bb);
        }
    }
}

// ---------------------------------------------------------------------------
// Kernel 2: fused attention — FMA-bound rewrite.
// Layouts (float4 units):
//   qs_v[32][65]: qs_v[d4][r]  = q[r][4*d4..4*d4+3]   (stride 65 -> bank-step 4,
//   ks_v[32][65]: ks_v[d4][j]                          conflict-free STS/LDS.128)
//   as  [64][64]: attn tile (fp32)
//   vs  [64][256]: v tile row-major
// sim: thread (ty,tx) ty=t>>4 tx=t&15: rows ty*4+u, cols tx+16c.
//      per d4: 8 LDS.128 + 64 FFMA.
// PV:  warp w rows w*8.., lane covers h=lane*4..+3 and h=128+lane*4..+3.
// ---------------------------------------------------------------------------
#define F4S 65
#define AT  64
#define Q_F4   (32*F4S)
#define K_F4   (32*F4S)
#define AS_OFF (2*Q_F4*4)              // float offset of as
#define VS_OFF (AS_OFF + 64*AT)        // float offset of vs
#define SMEM_BYTES ((VS_OFF + 64*256) * 4)

__global__ void __launch_bounds__(256, 1) k_attn(
    const float* __restrict__ Wout, const float* __restrict__ bout,
    float* __restrict__ out, float* __restrict__ att)
{
    extern __shared__ float sm[];
    float4* qs_v = reinterpret_cast<float4*>(sm);
    float4* ks_v = qs_v + Q_F4;
    float*  as   = sm + AS_OFF;
    float4* as4  = reinterpret_cast<float4*>(as);
    float*  vs   = sm + VS_OFF;
    float4* vs4  = reinterpret_cast<float4*>(vs);

    const int t  = threadIdx.x;
    const int b  = blockIdx.y;
    const int i0 = blockIdx.x * 64;
    const long tbase = (long)b * SS;
    float4* attb4 = reinterpret_cast<float4*>(att + (size_t)b * SS * SS);

    const float4* gq4 = reinterpret_cast<const float4*>(g_q);
    const float4* gk4 = reinterpret_cast<const float4*>(g_k);
    const float4* gv4 = reinterpret_cast<const float4*>(g_v);

    // load q tile, transposed into qs_v[d4][r]
    for (int i = t; i < 64 * 32; i += 256) {
        const int r = i >> 5, d4 = i & 31;
        qs_v[d4 * F4S + r] = gq4[(tbase + i0 + r) * 32 + d4];
    }

    float o[8][8];
    #pragma unroll
    for (int a = 0; a < 8; ++a)
        #pragma unroll
        for (int c = 0; c < 8; ++c) o[a][c] = 0.0f;

    const int ty = t >> 4, tx = t & 15;    // sim mapping
    const int w  = t >> 5, lane = t & 31;  // PV mapping
    const float invS = 1.0f / (float)SS;

    for (int j0 = 0; j0 < SS; j0 += 64) {
        __syncthreads();   // protect ks_v/vs/as reuse (and qs_v on iter 0)

        for (int i = t; i < 64 * 32; i += 256) {
            const int r = i >> 5, d4 = i & 31;
            ks_v[d4 * F4S + r] = gk4[(tbase + j0 + r) * 32 + d4];
        }
        for (int i = t; i < 64 * 64; i += 256)
            vs4[i] = gv4[(tbase + j0) * 64 + i];
        __syncthreads();

        // ---- sim: rows ty*4+u, cols tx+16c; 8 LDS.128 + 64 FFMA per d4 ----
        float acc[4][4];
        #pragma unroll
        for (int u = 0; u < 4; ++u)
            #pragma unroll
            for (int c = 0; c < 4; ++c) acc[u][c] = 0.0f;

        #pragma unroll 4
        for (int d4 = 0; d4 < 32; ++d4) {
            const float4 q0 = qs_v[d4 * F4S + ty * 4 + 0];
            const float4 q1 = qs_v[d4 * F4S + ty * 4 + 1];
            const float4 q2 = qs_v[d4 * F4S + ty * 4 + 2];
            const float4 q3 = qs_v[d4 * F4S + ty * 4 + 3];
            const float4 k0 = ks_v[d4 * F4S + tx];
            const float4 k1 = ks_v[d4 * F4S + tx + 16];
            const float4 k2 = ks_v[d4 * F4S + tx + 32];
            const float4 k3 = ks_v[d4 * F4S + tx + 48];
            #define DOT4(a, qv, kv) \
                a += qv.x*kv.x; a += qv.y*kv.y; a += qv.z*kv.z; a += qv.w*kv.w;
            DOT4(acc[0][0], q0, k0) DOT4(acc[0][1], q0, k1)
            DOT4(acc[0][2], q0, k2) DOT4(acc[0][3], q0, k3)
            DOT4(acc[1][0], q1, k0) DOT4(acc[1][1], q1, k1)
            DOT4(acc[1][2], q1, k2) DOT4(acc[1][3], q1, k3)
            DOT4(acc[2][0], q2, k0) DOT4(acc[2][1], q2, k1)
            DOT4(acc[2][2], q2, k2) DOT4(acc[2][3], q2, k3)
            DOT4(acc[3][0], q3, k0) DOT4(acc[3][1], q3, k1)
            DOT4(acc[3][2], q3, k2) DOT4(acc[3][3], q3, k3)
            #undef DOT4
        }

        // relu^2 -> as (cols tx+16c: lane-contiguous scalar stores)
        #pragma unroll
        for (int u = 0; u < 4; ++u) {
            #pragma unroll
            for (int c = 0; c < 4; ++c) {
                float x = fmaxf(acc[u][c], 0.0f) * invS;
                as[(ty * 4 + u) * AT + tx + 16 * c] = x * x;
            }
        }
        __syncthreads();

        // att_map tile write (coalesced float4)
        for (int i = t; i < 64 * 16; i += 256) {
            const int row = i >> 4, c4 = i & 15;
            attb4[(size_t)(i0 + row) * (SS / 4) + (j0 >> 2) + c4] =
                as4[row * 16 + c4];
        }

        // ---- PV: o[8][8] += attn @ v ----
        #pragma unroll 2
        for (int jb = 0; jb < 64; ++jb) {
            const float4 v0 = vs4[jb * 64 + lane];        // h = lane*4
            const float4 v1 = vs4[jb * 64 + 32 + lane];   // h = 128 + lane*4
            #pragma unroll
            for (int rr = 0; rr < 8; ++rr) {
                const float a = as[(w * 8 + rr) * AT + jb];  // broadcast
                o[rr][0] += a * v0.x; o[rr][1] += a * v0.y;
                o[rr][2] += a * v0.z; o[rr][3] += a * v0.w;
                o[rr][4] += a * v1.x; o[rr][5] += a * v1.y;
                o[rr][6] += a * v1.z; o[rr][7] += a * v1.w;
            }
        }
    }

    // ---- epilogue: og = o*gate into smem (reuse vs), then @ W_out + b ----
    __syncthreads();
    const float4* gg4 = reinterpret_cast<const float4*>(g_gate);
    #pragma unroll
    for (int rr = 0; rr < 8; ++rr) {
        const long g = tbase + i0 + w * 8 + rr;
        const float4 g0v = gg4[g * 64 + lane];        // h = lane*4
        const float4 g1v = gg4[g * 64 + 32 + lane];   // h = 128 + lane*4
        float4 a, bq;
        a.x  = o[rr][0] * g0v.x; a.y  = o[rr][1] * g0v.y;
        a.z  = o[rr][2] * g0v.z; a.w  = o[rr][3] * g0v.w;
        bq.x = o[rr][4] * g1v.x; bq.y = o[rr][5] * g1v.y;
        bq.z = o[rr][6] * g1v.z; bq.w = o[rr][7] * g1v.w;
        vs4[(w * 8 + rr) * 64 + lane]      = a;
        vs4[(w * 8 + rr) * 64 + 32 + lane] = bq;
    }
    __syncthreads();

    {
        const int c = t & 127, r0 = t >> 7;
        float acc2[32];
        #pragma unroll
        for (int i = 0; i < 32; ++i) acc2[i] = 0.0f;
        for (int h = 0; h < 256; ++h) {
            const float wv = Wout[h * 128 + c];
            #pragma unroll
            for (int i = 0; i < 32; ++i)
                acc2[i] += vs[(r0 + 2 * i) * 256 + h] * wv;  // broadcast
        }
        const float bb = bout[c];
        #pragma unroll
        for (int i = 0; i < 32; ++i)
            out[(tbase + i0 + r0 + 2 * i) * 128 + c] = acc2[i] + bb;
    }
}

// ---------------------------------------------------------------------------
extern "C" void kernel_launch(void* const* d_in, const int* in_sizes, int n_in,
                              void* d_out, int out_size)
{
    const float* query = (const float*)d_in[0];
    const float* value = (const float*)d_in[2];
    const float* ln_g  = (const float*)d_in[3];
    const float* ln_b  = (const float*)d_in[4];
    const float* Wg    = (const float*)d_in[5];
    const float* bg    = (const float*)d_in[6];
    const float* Wqk   = (const float*)d_in[7];
    const float* bqk   = (const float*)d_in[8];
    const float* gam   = (const float*)d_in[9];
    const float* bet   = (const float*)d_in[10];
    const float* Wout  = (const float*)d_in[11];
    const float* bout  = (const float*)d_in[12];

    float* out = (float*)d_out;                       // [B,S,D] first
    float* att = out + (size_t)BB * SS * DD;          // then [B,S,S]

    cudaFuncSetAttribute(k_attn, cudaFuncAttributeMaxDynamicSharedMemorySize,
                         SMEM_BYTES);

    k_pre<<<NTOK / 16, 256>>>(query, value, ln_g, ln_b, Wg, bg, Wqk, bqk, gam, bet);

    dim3 g2(SS / 64, BB);
    k_attn<<<g2, 256, SMEM_BYTES>>>(Wout, bout, out, att);
}

// round 4
// speedup vs baseline: 2.5688x; 2.4254x over previous
#include <cuda_runtime.h>
#include <cuda_bf16.h>
#include <math.h>
#include <stdint.h>

#define BB 4
#define SS 4096
#define DD 128
#define HH 256
#define NTOK (BB*SS)

// Split-bf16 operands (device globals: allocation-free rule)
__device__ __align__(16) __nv_bfloat16 g_qh[NTOK*DD];   // [tok][d]
__device__ __align__(16) __nv_bfloat16 g_ql[NTOK*DD];
__device__ __align__(16) __nv_bfloat16 g_kh[NTOK*DD];
__device__ __align__(16) __nv_bfloat16 g_kl[NTOK*DD];
__device__ __align__(16) __nv_bfloat16 g_vh[NTOK*HH];   // [b][h][s]  (transposed!)
__device__ __align__(16) __nv_bfloat16 g_vl[NTOK*HH];
__device__ float g_gate[NTOK*HH];                        // [tok][h] fp32

__device__ __forceinline__ float silu_f(float x) {
    return x / (1.0f + expf(-x));
}

__device__ __forceinline__ void bsplit(float x, unsigned short& hi, unsigned short& lo) {
    __nv_bfloat16 h = __float2bfloat16(x);
    __nv_bfloat16 l = __float2bfloat16(x - __bfloat162float(h));
    hi = __bfloat16_as_ushort(h);
    lo = __bfloat16_as_ushort(l);
}

#define LDSM4(r0, r1, r2, r3, a)                                              \
    asm volatile("ldmatrix.sync.aligned.m8n8.x4.shared.b16 {%0,%1,%2,%3},[%4];" \
                 : "=r"(r0), "=r"(r1), "=r"(r2), "=r"(r3) : "r"(a));

#define MMA16816(d, a0, a1, a2, a3, b0, b1)                                   \
    asm volatile("mma.sync.aligned.m16n8k16.row.col.f32.bf16.bf16.f32 "       \
                 "{%0,%1,%2,%3},{%4,%5,%6,%7},{%8,%9},{%0,%1,%2,%3};"         \
                 : "+f"(d[0]), "+f"(d[1]), "+f"(d[2]), "+f"(d[3])             \
                 : "r"(a0), "r"(a1), "r"(a2), "r"(a3), "r"(b0), "r"(b1));

// ---------------------------------------------------------------------------
// Kernel 1: per-token preproc. Same math as passing R1/R2 kernel, but emits
// split-bf16 q/k (token-major) and v (transposed [b][h][s]), gate fp32.
// ---------------------------------------------------------------------------
__global__ void __launch_bounds__(256) k_pre(
    const float* __restrict__ q_in, const float* __restrict__ v_in,
    const float* __restrict__ ln_g, const float* __restrict__ ln_b,
    const float* __restrict__ Wg,   const float* __restrict__ bg,
    const float* __restrict__ Wqk,  const float* __restrict__ bqk,
    const float* __restrict__ gam,  const float* __restrict__ bet)
{
    __shared__ float nrm[16][128];
    __shared__ float val[16][128];

    const int t = threadIdx.x;
    const int w = t >> 5, l = t & 31;
    const long g0 = (long)blockIdx.x * 16;

    for (int u = 0; u < 2; ++u) {
        const int tok = w * 2 + u;
        const long g = g0 + tok;
        const int s = (int)(g & (SS - 1));

        float4 x = reinterpret_cast<const float4*>(q_in)[g * 32 + l];

        if (l < 8) {
            const float f0 = powf(10000.0f, -(float)(4 * l)     / 32.0f);
            const float f1 = powf(10000.0f, -(float)(4 * l + 2) / 32.0f);
            float s0, c0, s1, c1;
            sincosf((float)s * f0, &s0, &c0);
            sincosf((float)s * f1, &s1, &c1);
            float a = x.x, b2 = x.y;
            x.x = a * c0 - b2 * s0;  x.y = b2 * c0 + a * s0;
            a = x.z;  b2 = x.w;
            x.z = a * c1 - b2 * s1;  x.w = b2 * c1 + a * s1;
        }

        float sum = x.x + x.y + x.z + x.w;
        float sq  = x.x*x.x + x.y*x.y + x.z*x.z + x.w*x.w;
        #pragma unroll
        for (int o = 16; o > 0; o >>= 1) {
            sum += __shfl_xor_sync(0xffffffffu, sum, o);
            sq  += __shfl_xor_sync(0xffffffffu, sq,  o);
        }
        const float mu  = sum * (1.0f / 128.0f);
        const float var = sq  * (1.0f / 128.0f) - mu * mu;
        const float rs  = rsqrtf(var + 1e-5f);

        const int d0 = 4 * l;
        float4 n;
        n.x = (x.x - mu) * rs * ln_g[d0 + 0] + ln_b[d0 + 0];
        n.y = (x.y - mu) * rs * ln_g[d0 + 1] + ln_b[d0 + 1];
        n.z = (x.z - mu) * rs * ln_g[d0 + 2] + ln_b[d0 + 2];
        n.w = (x.w - mu) * rs * ln_g[d0 + 3] + ln_b[d0 + 3];
        reinterpret_cast<float4*>(&nrm[tok][0])[l] = n;
        reinterpret_cast<float4*>(&val[tok][0])[l] =
            reinterpret_cast<const float4*>(v_in)[g * 32 + l];
    }
    __syncthreads();

    {   // qk -> q,k (split bf16)
        const int c = t & 127, half = t >> 7;
        float acc[8];
        #pragma unroll
        for (int j = 0; j < 8; ++j) acc[j] = 0.0f;
        for (int k = 0; k < 128; ++k) {
            const float wv = Wqk[k * 128 + c];
            #pragma unroll
            for (int j = 0; j < 8; ++j)
                acc[j] += nrm[2 * j + half][k] * wv;
        }
        const float gz0 = gam[c], gz1 = gam[128 + c];
        const float bz0 = bet[c], bz1 = bet[128 + c];
        const float bb = bqk[c];
        #pragma unroll
        for (int j = 0; j < 8; ++j) {
            const long g = g0 + 2 * j + half;
            const float sl = silu_f(acc[j] + bb);
            const float qv = sl * gz0 + bz0;
            const float kv = sl * gz1 + bz1;
            unsigned short hi, lo;
            bsplit(qv, hi, lo);
            g_qh[g * 128 + c] = __ushort_as_bfloat16(hi);
            g_ql[g * 128 + c] = __ushort_as_bfloat16(lo);
            bsplit(kv, hi, lo);
            g_kh[g * 128 + c] = __ushort_as_bfloat16(hi);
            g_kl[g * 128 + c] = __ushort_as_bfloat16(lo);
        }
    }

    {   // gate (fp32), v (split bf16, transposed [b][h][s])
        const int c = t;
        const int bidx = (int)(g0 >> 12);
        const int s0   = (int)(g0 & (SS - 1));
        float ag[16], av[16];
        #pragma unroll
        for (int j = 0; j < 16; ++j) { ag[j] = 0.0f; av[j] = 0.0f; }
        for (int k = 0; k < 128; ++k) {
            const float wv = Wg[k * 256 + c];
            #pragma unroll
            for (int j = 0; j < 16; ++j) {
                ag[j] += nrm[j][k] * wv;
                av[j] += val[j][k] * wv;
            }
        }
        const float bb = bg[c];
        #pragma unroll
        for (int j = 0; j < 16; ++j) {
            const long g = g0 + j;
            g_gate[g * 256 + c] = silu_f(ag[j] + bb);
            const float vv = silu_f(av[j] + bb);
            unsigned short hi, lo;
            bsplit(vv, hi, lo);
            const size_t vidx = ((size_t)bidx * HH + c) * SS + s0 + j;
            g_vh[vidx] = __ushort_as_bfloat16(hi);
            g_vl[vidx] = __ushort_as_bfloat16(lo);
        }
    }
}

// ---------------------------------------------------------------------------
// Kernel 2: tensor-core attention (mma.sync m16n8k16 bf16, 3-MMA split).
// 128 q-rows per CTA, 512 threads (16 warps). Token tiles of 64.
// Warp w: wm=w&7 (q-row group of 16), wh=w>>3 (sim col-half / h-half).
// smem (halves), padded strides 136 / 72 -> conflict-free LDSM:
//   qs_hi/lo [128][136], ks_hi/lo [64][136], vs_hi/lo [256][72] (h-major),
//   as_hi/lo [128][72] (attn tile, bf16 split).
// ---------------------------------------------------------------------------
#define QS_H 0
#define QS_L (128*136)
#define KS_H (2*128*136)
#define KS_L (KS_H + 64*136)
#define VS_H (KS_L + 64*136)
#define VS_L (VS_H + 256*72)
#define AS_H (VS_L + 256*72)
#define AS_L (AS_H + 128*72)
#define SM_HALVES (AS_L + 128*72)
#define SMEM_BYTES (SM_HALVES*2)   // 215,040 B
#define OG_STRIDE 264

__global__ void __launch_bounds__(512, 1) k_attn(
    const float* __restrict__ Wout, const float* __restrict__ bout,
    float* __restrict__ out, float* __restrict__ att)
{
    extern __shared__ __align__(16) unsigned short sb[];

    const int t = threadIdx.x, w = t >> 5, l = t & 31;
    const int b = blockIdx.y, i0 = blockIdx.x * 128;
    const long tbase = (long)b * SS;
    const int wm = w & 7, wh = w >> 3;
    const int rm = wm * 16;

    // lane constants for ldmatrix addressing
    const int l15 = l & 15;
    const int lh  = (l >> 4) << 3;               // A: k-offset 0/8
    const int grp = l >> 3;
    const int brow2 = ((grp >> 1) << 3) + (l & 7);  // B: row within 2-tile pair
    const int bcol2 = (grp & 1) << 3;               // B: k-offset 0/8

    const uint32_t sbase = (uint32_t)__cvta_generic_to_shared(sb);

    const uint4* gq4h = (const uint4*)g_qh;
    const uint4* gq4l = (const uint4*)g_ql;
    const uint4* gk4h = (const uint4*)g_kh;
    const uint4* gk4l = (const uint4*)g_kl;
    const uint4* gv4h = (const uint4*)g_vh;
    const uint4* gv4l = (const uint4*)g_vl;

    // load q tile (hi/lo)
    for (int i = t; i < 128 * 16; i += 512) {
        const int r = i >> 4, c4 = i & 15;
        ((uint4*)(sb + QS_H))[r * 17 + c4] = gq4h[(tbase + i0 + r) * 16 + c4];
        ((uint4*)(sb + QS_L))[r * 17 + c4] = gq4l[(tbase + i0 + r) * 16 + c4];
    }

    float o[16][4];
    #pragma unroll
    for (int i = 0; i < 16; ++i)
        #pragma unroll
        for (int j = 0; j < 4; ++j) o[i][j] = 0.0f;

    float2* attb2 = (float2*)(att + (size_t)b * SS * SS);
    const float invS = 1.0f / (float)SS;

    for (int j0 = 0; j0 < SS; j0 += 64) {
        __syncthreads();   // protect ks/vs/as reuse from previous iter

        for (int i = t; i < 64 * 16; i += 512) {
            const int r = i >> 4, c4 = i & 15;
            ((uint4*)(sb + KS_H))[r * 17 + c4] = gk4h[(tbase + j0 + r) * 16 + c4];
            ((uint4*)(sb + KS_L))[r * 17 + c4] = gk4l[(tbase + j0 + r) * 16 + c4];
        }
        for (int i = t; i < 256 * 8; i += 512) {
            const int h = i >> 3, c4 = i & 7;
            const size_t src = ((size_t)b * HH + h) * (SS / 8) + (j0 >> 3) + c4;
            ((uint4*)(sb + VS_H))[h * 9 + c4] = gv4h[src];
            ((uint4*)(sb + VS_L))[h * 9 + c4] = gv4l[src];
        }
        __syncthreads();

        // ---- sim: rows rm..rm+15, cols cn..cn+31 ----
        float s[4][4];
        #pragma unroll
        for (int i = 0; i < 4; ++i)
            #pragma unroll
            for (int j = 0; j < 4; ++j) s[i][j] = 0.0f;

        const int cn = wh * 32;
        #pragma unroll
        for (int kk = 0; kk < 8; ++kk) {
            const int k0 = kk * 16;
            uint32_t ah0, ah1, ah2, ah3, al0, al1, al2, al3;
            LDSM4(ah0, ah1, ah2, ah3,
                  sbase + 2u * (QS_H + (rm + l15) * 136 + k0 + lh));
            LDSM4(al0, al1, al2, al3,
                  sbase + 2u * (QS_L + (rm + l15) * 136 + k0 + lh));

            uint32_t bh[8], bl[8];
            #pragma unroll
            for (int p = 0; p < 2; ++p) {
                LDSM4(bh[4*p+0], bh[4*p+1], bh[4*p+2], bh[4*p+3],
                      sbase + 2u * (KS_H + (cn + p*16 + brow2) * 136 + k0 + bcol2));
                LDSM4(bl[4*p+0], bl[4*p+1], bl[4*p+2], bl[4*p+3],
                      sbase + 2u * (KS_L + (cn + p*16 + brow2) * 136 + k0 + bcol2));
            }
            #pragma unroll
            for (int nt = 0; nt < 4; ++nt) {
                MMA16816(s[nt], ah0, ah1, ah2, ah3, bh[2*nt], bh[2*nt+1]);
                MMA16816(s[nt], ah0, ah1, ah2, ah3, bl[2*nt], bl[2*nt+1]);
                MMA16816(s[nt], al0, al1, al2, al3, bh[2*nt], bh[2*nt+1]);
            }
        }

        // ---- relu^2/S^2: write att (global) + as_hi/as_lo (smem) ----
        const int ra = rm + (l >> 2);
        const int rb = ra + 8;
        #pragma unroll
        for (int nt = 0; nt < 4; ++nt) {
            const int colg = cn + nt * 8 + 2 * (l & 3);
            float x;
            x = fmaxf(s[nt][0], 0.0f) * invS; const float a0 = x * x;
            x = fmaxf(s[nt][1], 0.0f) * invS; const float a1 = x * x;
            x = fmaxf(s[nt][2], 0.0f) * invS; const float a2 = x * x;
            x = fmaxf(s[nt][3], 0.0f) * invS; const float a3 = x * x;

            attb2[((size_t)(i0 + ra) * SS + j0 + colg) >> 1] = make_float2(a0, a1);
            attb2[((size_t)(i0 + rb) * SS + j0 + colg) >> 1] = make_float2(a2, a3);

            unsigned short h0, h1, q0, q1;
            bsplit(a0, h0, q0); bsplit(a1, h1, q1);
            *(uint32_t*)(sb + AS_H + ra * 72 + colg) = (uint32_t)h0 | ((uint32_t)h1 << 16);
            *(uint32_t*)(sb + AS_L + ra * 72 + colg) = (uint32_t)q0 | ((uint32_t)q1 << 16);
            bsplit(a2, h0, q0); bsplit(a3, h1, q1);
            *(uint32_t*)(sb + AS_H + rb * 72 + colg) = (uint32_t)h0 | ((uint32_t)h1 << 16);
            *(uint32_t*)(sb + AS_L + rb * 72 + colg) = (uint32_t)q0 | ((uint32_t)q1 << 16);
        }
        __syncthreads();

        // ---- PV: o[rows rm..rm+15][h = wh*128 .. +127] += attn @ v ----
        #pragma unroll
        for (int kt = 0; kt < 4; ++kt) {
            const int tok0 = kt * 16;
            uint32_t ah0, ah1, ah2, ah3, al0, al1, al2, al3;
            LDSM4(ah0, ah1, ah2, ah3,
                  sbase + 2u * (AS_H + (rm + l15) * 72 + tok0 + lh));
            LDSM4(al0, al1, al2, al3,
                  sbase + 2u * (AS_L + (rm + l15) * 72 + tok0 + lh));

            #pragma unroll
            for (int hp = 0; hp < 8; ++hp) {
                const int h0 = wh * 128 + hp * 16;
                uint32_t vh0, vh1, vh2, vh3, vl0, vl1, vl2, vl3;
                LDSM4(vh0, vh1, vh2, vh3,
                      sbase + 2u * (VS_H + (h0 + brow2) * 72 + tok0 + bcol2));
                LDSM4(vl0, vl1, vl2, vl3,
                      sbase + 2u * (VS_L + (h0 + brow2) * 72 + tok0 + bcol2));

                MMA16816(o[hp*2],   ah0, ah1, ah2, ah3, vh0, vh1);
                MMA16816(o[hp*2],   ah0, ah1, ah2, ah3, vl0, vl1);
                MMA16816(o[hp*2],   al0, al1, al2, al3, vh0, vh1);
                MMA16816(o[hp*2+1], ah0, ah1, ah2, ah3, vh2, vh3);
                MMA16816(o[hp*2+1], ah0, ah1, ah2, ah3, vl2, vl3);
                MMA16816(o[hp*2+1], al0, al1, al2, al3, vh2, vh3);
            }
        }
    }

    // ---- epilogue: og = o*gate -> smem (reuse), then @ W_out + b ----
    __syncthreads();
    float* og = (float*)sb;
    {
        const int ra = rm + (l >> 2);
        #pragma unroll
        for (int ht = 0; ht < 16; ++ht) {
            const int hc = wh * 128 + ht * 8 + 2 * (l & 3);
            const float2 ga = *(const float2*)&g_gate[(tbase + i0 + ra) * 256 + hc];
            const float2 gb = *(const float2*)&g_gate[(tbase + i0 + ra + 8) * 256 + hc];
            *(float2*)&og[ra * OG_STRIDE + hc] =
                make_float2(o[ht][0] * ga.x, o[ht][1] * ga.y);
            *(float2*)&og[(ra + 8) * OG_STRIDE + hc] =
                make_float2(o[ht][2] * gb.x, o[ht][3] * gb.y);
        }
    }
    __syncthreads();

    {
        const int c = t & 127, r0 = t >> 7;
        float acc2[32];
        #pragma unroll
        for (int i = 0; i < 32; ++i) acc2[i] = 0.0f;
        for (int h = 0; h < 256; ++h) {
            const float wv = Wout[h * 128 + c];
            #pragma unroll
            for (int i = 0; i < 32; ++i)
                acc2[i] += og[(r0 + 4 * i) * OG_STRIDE + h] * wv;  // broadcast
        }
        const float bb = bout[c];
        #pragma unroll
        for (int i = 0; i < 32; ++i)
            out[(tbase + i0 + r0 + 4 * i) * 128 + c] = acc2[i] + bb;
    }
}

// ---------------------------------------------------------------------------
extern "C" void kernel_launch(void* const* d_in, const int* in_sizes, int n_in,
                              void* d_out, int out_size)
{
    const float* query = (const float*)d_in[0];
    const float* value = (const float*)d_in[2];
    const float* ln_g  = (const float*)d_in[3];
    const float* ln_b  = (const float*)d_in[4];
    const float* Wg    = (const float*)d_in[5];
    const float* bg    = (const float*)d_in[6];
    const float* Wqk   = (const float*)d_in[7];
    const float* bqk   = (const float*)d_in[8];
    const float* gam   = (const float*)d_in[9];
    const float* bet   = (const float*)d_in[10];
    const float* Wout  = (const float*)d_in[11];
    const float* bout  = (const float*)d_in[12];

    float* out = (float*)d_out;                       // [B,S,D] first
    float* att = out + (size_t)BB * SS * DD;          // then [B,S,S]

    cudaFuncSetAttribute(k_attn, cudaFuncAttributeMaxDynamicSharedMemorySize,
                         SMEM_BYTES);

    k_pre<<<NTOK / 16, 256>>>(query, value, ln_g, ln_b, Wg, bg, Wqk, bqk, gam, bet);

    dim3 g2(SS / 128, BB);
    k_attn<<<g2, 512, SMEM_BYTES>>>(Wout, bout, out, att);
}

// round 6
// speedup vs baseline: 2.9825x; 1.1610x over previous
#include <cuda_runtime.h>
#include <cuda_bf16.h>
#include <math.h>
#include <stdint.h>

#define BB 4
#define SS 4096
#define DD 128
#define HH 256
#define NTOK (BB*SS)
#define NT (SS/64)

// Split-bf16 operands (device globals: allocation-free rule)
__device__ __align__(16) __nv_bfloat16 g_qh[NTOK*DD];   // [tok][d]
__device__ __align__(16) __nv_bfloat16 g_ql[NTOK*DD];
__device__ __align__(16) __nv_bfloat16 g_kh[NTOK*DD];
__device__ __align__(16) __nv_bfloat16 g_kl[NTOK*DD];
__device__ __align__(16) __nv_bfloat16 g_vh[NTOK*HH];   // [b][h][s]  (transposed)
__device__ __align__(16) __nv_bfloat16 g_vl[NTOK*HH];
__device__ float g_gate[NTOK*HH];                        // [tok][h] fp32

__device__ __forceinline__ float silu_f(float x) {
    return x / (1.0f + expf(-x));
}

__device__ __forceinline__ void bsplit(float x, unsigned short& hi, unsigned short& lo) {
    __nv_bfloat16 h = __float2bfloat16(x);
    __nv_bfloat16 l = __float2bfloat16(x - __bfloat162float(h));
    hi = __bfloat16_as_ushort(h);
    lo = __bfloat16_as_ushort(l);
}

#define LDSM4(r0, r1, r2, r3, a)                                              \
    asm volatile("ldmatrix.sync.aligned.m8n8.x4.shared.b16 {%0,%1,%2,%3},[%4];" \
                 : "=r"(r0), "=r"(r1), "=r"(r2), "=r"(r3) : "r"(a));

#define MMA16816(d, a0, a1, a2, a3, b0, b1)                                   \
    asm volatile("mma.sync.aligned.m16n8k16.row.col.f32.bf16.bf16.f32 "       \
                 "{%0,%1,%2,%3},{%4,%5,%6,%7},{%8,%9},{%0,%1,%2,%3};"         \
                 : "+f"(d[0]), "+f"(d[1]), "+f"(d[2]), "+f"(d[3])             \
                 : "r"(a0), "r"(a1), "r"(a2), "r"(a3), "r"(b0), "r"(b1));

#define CP16(dst, src) \
    asm volatile("cp.async.cg.shared.global [%0], [%1], 16;" \
                 :: "r"(dst), "l"(src) : "memory")
#define CP_COMMIT() asm volatile("cp.async.commit_group;" ::: "memory")
#define CP_WAIT(n)  asm volatile("cp.async.wait_group %0;" :: "n"(n) : "memory")

// ---------------------------------------------------------------------------
// Kernel 1: per-token preproc (unchanged from passing R3 kernel).
// ---------------------------------------------------------------------------
__global__ void __launch_bounds__(256) k_pre(
    const float* __restrict__ q_in, const float* __restrict__ v_in,
    const float* __restrict__ ln_g, const float* __restrict__ ln_b,
    const float* __restrict__ Wg,   const float* __restrict__ bg,
    const float* __restrict__ Wqk,  const float* __restrict__ bqk,
    const float* __restrict__ gam,  const float* __restrict__ bet)
{
    __shared__ float nrm[16][128];
    __shared__ float val[16][128];

    const int t = threadIdx.x;
    const int w = t >> 5, l = t & 31;
    const long g0 = (long)blockIdx.x * 16;

    for (int u = 0; u < 2; ++u) {
        const int tok = w * 2 + u;
        const long g = g0 + tok;
        const int s = (int)(g & (SS - 1));

        float4 x = reinterpret_cast<const float4*>(q_in)[g * 32 + l];

        if (l < 8) {
            const float f0 = powf(10000.0f, -(float)(4 * l)     / 32.0f);
            const float f1 = powf(10000.0f, -(float)(4 * l + 2) / 32.0f);
            float s0, c0, s1, c1;
            sincosf((float)s * f0, &s0, &c0);
            sincosf((float)s * f1, &s1, &c1);
            float a = x.x, b2 = x.y;
            x.x = a * c0 - b2 * s0;  x.y = b2 * c0 + a * s0;
            a = x.z;  b2 = x.w;
            x.z = a * c1 - b2 * s1;  x.w = b2 * c1 + a * s1;
        }

        float sum = x.x + x.y + x.z + x.w;
        float sq  = x.x*x.x + x.y*x.y + x.z*x.z + x.w*x.w;
        #pragma unroll
        for (int o = 16; o > 0; o >>= 1) {
            sum += __shfl_xor_sync(0xffffffffu, sum, o);
            sq  += __shfl_xor_sync(0xffffffffu, sq,  o);
        }
        const float mu  = sum * (1.0f / 128.0f);
        const float var = sq  * (1.0f / 128.0f) - mu * mu;
        const float rs  = rsqrtf(var + 1e-5f);

        const int d0 = 4 * l;
        float4 n;
        n.x = (x.x - mu) * rs * ln_g[d0 + 0] + ln_b[d0 + 0];
        n.y = (x.y - mu) * rs * ln_g[d0 + 1] + ln_b[d0 + 1];
        n.z = (x.z - mu) * rs * ln_g[d0 + 2] + ln_b[d0 + 2];
        n.w = (x.w - mu) * rs * ln_g[d0 + 3] + ln_b[d0 + 3];
        reinterpret_cast<float4*>(&nrm[tok][0])[l] = n;
        reinterpret_cast<float4*>(&val[tok][0])[l] =
            reinterpret_cast<const float4*>(v_in)[g * 32 + l];
    }
    __syncthreads();

    {   // qk -> q,k (split bf16)
        const int c = t & 127, half = t >> 7;
        float acc[8];
        #pragma unroll
        for (int j = 0; j < 8; ++j) acc[j] = 0.0f;
        for (int k = 0; k < 128; ++k) {
            const float wv = Wqk[k * 128 + c];
            #pragma unroll
            for (int j = 0; j < 8; ++j)
                acc[j] += nrm[2 * j + half][k] * wv;
        }
        const float gz0 = gam[c], gz1 = gam[128 + c];
        const float bz0 = bet[c], bz1 = bet[128 + c];
        const float bb = bqk[c];
        #pragma unroll
        for (int j = 0; j < 8; ++j) {
            const long g = g0 + 2 * j + half;
            const float sl = silu_f(acc[j] + bb);
            const float qv = sl * gz0 + bz0;
            const float kv = sl * gz1 + bz1;
            unsigned short hi, lo;
            bsplit(qv, hi, lo);
            g_qh[g * 128 + c] = __ushort_as_bfloat16(hi);
            g_ql[g * 128 + c] = __ushort_as_bfloat16(lo);
            bsplit(kv, hi, lo);
            g_kh[g * 128 + c] = __ushort_as_bfloat16(hi);
            g_kl[g * 128 + c] = __ushort_as_bfloat16(lo);
        }
    }

    {   // gate (fp32), v (split bf16, transposed [b][h][s])
        const int c = t;
        const int bidx = (int)(g0 >> 12);
        const int s0   = (int)(g0 & (SS - 1));
        float ag[16], av[16];
        #pragma unroll
        for (int j = 0; j < 16; ++j) { ag[j] = 0.0f; av[j] = 0.0f; }
        for (int k = 0; k < 128; ++k) {
            const float wv = Wg[k * 256 + c];
            #pragma unroll
            for (int j = 0; j < 16; ++j) {
                ag[j] += nrm[j][k] * wv;
                av[j] += val[j][k] * wv;
            }
        }
        const float bb = bg[c];
        #pragma unroll
        for (int j = 0; j < 16; ++j) {
            const long g = g0 + j;
            g_gate[g * 256 + c] = silu_f(ag[j] + bb);
            const float vv = silu_f(av[j] + bb);
            unsigned short hi, lo;
            bsplit(vv, hi, lo);
            const size_t vidx = ((size_t)bidx * HH + c) * SS + s0 + j;
            g_vh[vidx] = __ushort_as_bfloat16(hi);
            g_vl[vidx] = __ushort_as_bfloat16(lo);
        }
    }
}

// ---------------------------------------------------------------------------
// Kernel 2: HMMA attention, pipelined. 128 q-rows/CTA, 512 threads, 16 warps.
// sim: warp (wm=w&7 -> 16 rows, wh=w>>3 -> 32 cols). 3-MMA bf16 split.
// PV:  warp (wr=w&3 -> 32 rows, wc=w>>2 -> 64 h).     3-MMA bf16 split.
// cp.async: v(it) prefetched during sim(it); k(it+1) during PV(it).
// smem halves (ushort units), padded strides 136 / 72 (conflict-free LDSM).
// ---------------------------------------------------------------------------
#define QS_H 0
#define QS_L (128*136)
#define KS_H (2*128*136)
#define KS_L (KS_H + 64*136)
#define VS_H (KS_L + 64*136)
#define VS_L (VS_H + 256*72)
#define AS_H (VS_L + 256*72)
#define AS_L (AS_H + 128*72)
#define SM_HALVES (AS_L + 128*72)
#define SMEM_BYTES (SM_HALVES*2)   // 215,040 B
#define OGS 264

__global__ void __launch_bounds__(512, 1) k_attn(
    const float* __restrict__ Wout, const float* __restrict__ bout,
    float* __restrict__ out, float* __restrict__ att)
{
    extern __shared__ __align__(16) unsigned short sb[];

    const int t = threadIdx.x, w = t >> 5, l = t & 31;
    const int b = blockIdx.y, i0 = blockIdx.x * 128;
    const long tbase = (long)b * SS;
    const int wm = w & 7, wh = w >> 3;          // sim mapping
    const int rm = wm * 16, cn = wh * 32;
    const int wr = w & 3, wc = w >> 2;          // PV mapping
    const int pr = wr * 32, ph = wc * 64;

    const int l15 = l & 15;
    const int lh  = (l >> 4) << 3;
    const int grp = l >> 3;
    const int brow2 = ((grp >> 1) << 3) + (l & 7);
    const int bcol2 = (grp & 1) << 3;

    const uint32_t sbase = (uint32_t)__cvta_generic_to_shared(sb);

    const uint4* gq4h = (const uint4*)g_qh;
    const uint4* gq4l = (const uint4*)g_ql;
    const uint4* gk4h = (const uint4*)g_kh;
    const uint4* gk4l = (const uint4*)g_kl;
    const uint4* gv4h = (const uint4*)g_vh;
    const uint4* gv4l = (const uint4*)g_vl;

    // ---- prologue: prefetch k(0), then load q tile ----
    {
        const int r = t >> 3, c4a = (t & 7) * 2;   // 64 rows x 16 uint4, 2/thread
        CP16(sbase + 2u*KS_H + (uint32_t)(r*17 + c4a    )*16,
             (const void*)&gk4h[(tbase + r) * 16 + c4a]);
        CP16(sbase + 2u*KS_H + (uint32_t)(r*17 + c4a + 1)*16,
             (const void*)&gk4h[(tbase + r) * 16 + c4a + 1]);
        CP16(sbase + 2u*KS_L + (uint32_t)(r*17 + c4a    )*16,
             (const void*)&gk4l[(tbase + r) * 16 + c4a]);
        CP16(sbase + 2u*KS_L + (uint32_t)(r*17 + c4a + 1)*16,
             (const void*)&gk4l[(tbase + r) * 16 + c4a + 1]);
        CP_COMMIT();
    }
    for (int i = t; i < 128 * 16; i += 512) {
        const int r = i >> 4, c4 = i & 15;
        ((uint4*)(sb + QS_H))[r * 17 + c4] = gq4h[(tbase + i0 + r) * 16 + c4];
        ((uint4*)(sb + QS_L))[r * 17 + c4] = gq4l[(tbase + i0 + r) * 16 + c4];
    }

    float o[2][8][4];
    #pragma unroll
    for (int a = 0; a < 2; ++a)
        #pragma unroll
        for (int j = 0; j < 8; ++j)
            #pragma unroll
            for (int c = 0; c < 4; ++c) o[a][j][c] = 0.0f;

    float2* attb2 = (float2*)(att + (size_t)b * SS * SS);
    const float invS = 1.0f / (float)SS;

    for (int it = 0; it < NT; ++it) {
        const int j0 = it * 64;

        CP_WAIT(0);          // k(it) resident
        __syncthreads();     // all warps past PV(it-1); k visible to all

        // prefetch v(it): overlaps sim + convert
        {
            const int h = t >> 1, c4a = (t & 1) * 4;   // 256 rows x 8 uint4
            const size_t src = ((size_t)b * HH + h) * (SS / 8) + (j0 >> 3) + c4a;
            #pragma unroll
            for (int u = 0; u < 4; ++u) {
                CP16(sbase + 2u*VS_H + (uint32_t)(h*9 + c4a + u)*16,
                     (const void*)&gv4h[src + u]);
                CP16(sbase + 2u*VS_L + (uint32_t)(h*9 + c4a + u)*16,
                     (const void*)&gv4l[src + u]);
            }
            CP_COMMIT();
        }

        // ---- sim: rows rm..+15, cols cn..+31, 3-MMA split ----
        float s[4][4];
        #pragma unroll
        for (int i = 0; i < 4; ++i)
            #pragma unroll
            for (int j = 0; j < 4; ++j) s[i][j] = 0.0f;

        #pragma unroll
        for (int kk = 0; kk < 8; ++kk) {
            const int k0 = kk * 16;
            uint32_t ah0, ah1, ah2, ah3, al0, al1, al2, al3, bb[8];
            LDSM4(ah0, ah1, ah2, ah3, sbase + 2u*(QS_H + (rm + l15)*136 + k0 + lh));
            LDSM4(al0, al1, al2, al3, sbase + 2u*(QS_L + (rm + l15)*136 + k0 + lh));
            LDSM4(bb[0], bb[1], bb[2], bb[3],
                  sbase + 2u*(KS_H + (cn + brow2)*136 + k0 + bcol2));
            LDSM4(bb[4], bb[5], bb[6], bb[7],
                  sbase + 2u*(KS_H + (cn + 16 + brow2)*136 + k0 + bcol2));
            #pragma unroll
            for (int nt = 0; nt < 4; ++nt)
                MMA16816(s[nt], ah0, ah1, ah2, ah3, bb[2*nt], bb[2*nt+1]);
            #pragma unroll
            for (int nt = 0; nt < 4; ++nt)
                MMA16816(s[nt], al0, al1, al2, al3, bb[2*nt], bb[2*nt+1]);
            LDSM4(bb[0], bb[1], bb[2], bb[3],
                  sbase + 2u*(KS_L + (cn + brow2)*136 + k0 + bcol2));
            LDSM4(bb[4], bb[5], bb[6], bb[7],
                  sbase + 2u*(KS_L + (cn + 16 + brow2)*136 + k0 + bcol2));
            #pragma unroll
            for (int nt = 0; nt < 4; ++nt)
                MMA16816(s[nt], ah0, ah1, ah2, ah3, bb[2*nt], bb[2*nt+1]);
        }

        // ---- relu^2/S^2: write att (global) + as_hi/as_lo (smem) ----
        {
            const int ra = rm + (l >> 2);
            const int rb = ra + 8;
            #pragma unroll
            for (int nt = 0; nt < 4; ++nt) {
                const int colg = cn + nt * 8 + 2 * (l & 3);
                float x;
                x = fmaxf(s[nt][0], 0.0f) * invS; const float a0 = x * x;
                x = fmaxf(s[nt][1], 0.0f) * invS; const float a1 = x * x;
                x = fmaxf(s[nt][2], 0.0f) * invS; const float a2 = x * x;
                x = fmaxf(s[nt][3], 0.0f) * invS; const float a3 = x * x;

                attb2[((size_t)(i0 + ra) * SS + j0 + colg) >> 1] = make_float2(a0, a1);
                attb2[((size_t)(i0 + rb) * SS + j0 + colg) >> 1] = make_float2(a2, a3);

                unsigned short h0, h1, q0, q1;
                bsplit(a0, h0, q0); bsplit(a1, h1, q1);
                *(uint32_t*)(sb + AS_H + ra * 72 + colg) = (uint32_t)h0 | ((uint32_t)h1 << 16);
                *(uint32_t*)(sb + AS_L + ra * 72 + colg) = (uint32_t)q0 | ((uint32_t)q1 << 16);
                bsplit(a2, h0, q0); bsplit(a3, h1, q1);
                *(uint32_t*)(sb + AS_H + rb * 72 + colg) = (uint32_t)h0 | ((uint32_t)h1 << 16);
                *(uint32_t*)(sb + AS_L + rb * 72 + colg) = (uint32_t)q0 | ((uint32_t)q1 << 16);
            }
        }
        __syncthreads();     // as ready; k buffer free

        // prefetch k(it+1): overlaps PV
        if (it + 1 < NT) {
            const int r = t >> 3, c4a = (t & 7) * 2;
            CP16(sbase + 2u*KS_H + (uint32_t)(r*17 + c4a    )*16,
                 (const void*)&gk4h[(tbase + j0 + 64 + r) * 16 + c4a]);
            CP16(sbase + 2u*KS_H + (uint32_t)(r*17 + c4a + 1)*16,
                 (const void*)&gk4h[(tbase + j0 + 64 + r) * 16 + c4a + 1]);
            CP16(sbase + 2u*KS_L + (uint32_t)(r*17 + c4a    )*16,
                 (const void*)&gk4l[(tbase + j0 + 64 + r) * 16 + c4a]);
            CP16(sbase + 2u*KS_L + (uint32_t)(r*17 + c4a + 1)*16,
                 (const void*)&gk4l[(tbase + j0 + 64 + r) * 16 + c4a + 1]);
            CP_COMMIT();
            CP_WAIT(1);      // v(it) done; k(it+1) in flight
        } else {
            CP_WAIT(0);      // v(it) done
        }
        __syncthreads();     // v visible to all

        // ---- PV: rows pr..+31, h ph..+63, 3-MMA split ----
        #pragma unroll
        for (int kt = 0; kt < 4; ++kt) {
            const int tok0 = kt * 16;
            uint32_t Ah[8], Al[8], Bv[16];
            #pragma unroll
            for (int rg = 0; rg < 2; ++rg) {
                LDSM4(Ah[4*rg], Ah[4*rg+1], Ah[4*rg+2], Ah[4*rg+3],
                      sbase + 2u*(AS_H + (pr + rg*16 + l15)*72 + tok0 + lh));
                LDSM4(Al[4*rg], Al[4*rg+1], Al[4*rg+2], Al[4*rg+3],
                      sbase + 2u*(AS_L + (pr + rg*16 + l15)*72 + tok0 + lh));
            }
            #pragma unroll
            for (int hp = 0; hp < 4; ++hp)
                LDSM4(Bv[4*hp], Bv[4*hp+1], Bv[4*hp+2], Bv[4*hp+3],
                      sbase + 2u*(VS_H + (ph + hp*16 + brow2)*72 + tok0 + bcol2));
            #pragma unroll
            for (int rg = 0; rg < 2; ++rg)
                #pragma unroll
                for (int j = 0; j < 8; ++j)
                    MMA16816(o[rg][j], Ah[4*rg], Ah[4*rg+1], Ah[4*rg+2], Ah[4*rg+3],
                             Bv[2*j], Bv[2*j+1]);
            #pragma unroll
            for (int rg = 0; rg < 2; ++rg)
                #pragma unroll
                for (int j = 0; j < 8; ++j)
                    MMA16816(o[rg][j], Al[4*rg], Al[4*rg+1], Al[4*rg+2], Al[4*rg+3],
                             Bv[2*j], Bv[2*j+1]);
            #pragma unroll
            for (int hp = 0; hp < 4; ++hp)
                LDSM4(Bv[4*hp], Bv[4*hp+1], Bv[4*hp+2], Bv[4*hp+3],
                      sbase + 2u*(VS_L + (ph + hp*16 + brow2)*72 + tok0 + bcol2));
            #pragma unroll
            for (int rg = 0; rg < 2; ++rg)
                #pragma unroll
                for (int j = 0; j < 8; ++j)
                    MMA16816(o[rg][j], Ah[4*rg], Ah[4*rg+1], Ah[4*rg+2], Ah[4*rg+3],
                             Bv[2*j], Bv[2*j+1]);
        }
    }

    // ---- epilogue: og = o*gate -> smem (reuse), then @ W_out + b ----
    __syncthreads();
    float* og = (float*)sb;
    {
        const int ra0 = pr + (l >> 2);
        #pragma unroll
        for (int rg = 0; rg < 2; ++rg) {
            const int ra = ra0 + rg * 16;
            const int rb = ra + 8;
            #pragma unroll
            for (int j = 0; j < 8; ++j) {
                const int hc = ph + (j >> 1) * 16 + (j & 1) * 8 + 2 * (l & 3);
                const float2 ga = *(const float2*)&g_gate[(tbase + i0 + ra) * 256 + hc];
                const float2 gb = *(const float2*)&g_gate[(tbase + i0 + rb) * 256 + hc];
                *(float2*)&og[ra * OGS + hc] =
                    make_float2(o[rg][j][0] * ga.x, o[rg][j][1] * ga.y);
                *(float2*)&og[rb * OGS + hc] =
                    make_float2(o[rg][j][2] * gb.x, o[rg][j][3] * gb.y);
            }
        }
    }
    __syncthreads();

    {
        const int c = t & 127, r0 = t >> 7;
        float acc2[32];
        #pragma unroll
        for (int i = 0; i < 32; ++i) acc2[i] = 0.0f;
        for (int h = 0; h < 256; ++h) {
            const float wv = Wout[h * 128 + c];
            #pragma unroll
            for (int i = 0; i < 32; ++i)
                acc2[i] += og[(r0 + 4 * i) * OGS + h] * wv;  // smem broadcast
        }
        const float bb = bout[c];
        #pragma unroll
        for (int i = 0; i < 32; ++i)
            out[(tbase + i0 + r0 + 4 * i) * 128 + c] = acc2[i] + bb;
    }
}

// ---------------------------------------------------------------------------
extern "C" void kernel_launch(void* const* d_in, const int* in_sizes, int n_in,
                              void* d_out, int out_size)
{
    const float* query = (const float*)d_in[0];
    const float* value = (const float*)d_in[2];
    const float* ln_g  = (const float*)d_in[3];
    const float* ln_b  = (const float*)d_in[4];
    const float* Wg    = (const float*)d_in[5];
    const float* bg    = (const float*)d_in[6];
    const float* Wqk   = (const float*)d_in[7];
    const float* bqk   = (const float*)d_in[8];
    const float* gam   = (const float*)d_in[9];
    const float* bet   = (const float*)d_in[10];
    const float* Wout  = (const float*)d_in[11];
    const float* bout  = (const float*)d_in[12];

    float* out = (float*)d_out;                       // [B,S,D] first
    float* att = out + (size_t)BB * SS * DD;          // then [B,S,S]

    cudaFuncSetAttribute(k_attn, cudaFuncAttributeMaxDynamicSharedMemorySize,
                         SMEM_BYTES);

    k_pre<<<NTOK / 16, 256>>>(query, value, ln_g, ln_b, Wg, bg, Wqk, bqk, gam, bet);

    dim3 g2(SS / 128, BB);
    k_attn<<<g2, 512, SMEM_BYTES>>>(Wout, bout, out, att);
}

// round 7
// speedup vs baseline: 3.8705x; 1.2977x over previous
#include <cuda_runtime.h>
#include <cuda_bf16.h>
#include <cuda_fp16.h>
#include <math.h>
#include <stdint.h>

#define BB 4
#define SS 4096
#define DD 128
#define HH 256
#define NTOK (BB*SS)
#define NT (SS/64)

#define ASCALE 1073741824.0f          // 2^30 attn pre-scale for fp16 PV
#define INV_ASCALE (1.0f/1073741824.0f)

// Operands (device globals: allocation-free rule)
__device__ __align__(16) __nv_bfloat16 g_qh[NTOK*DD];   // [tok][d]
__device__ __align__(16) __nv_bfloat16 g_ql[NTOK*DD];
__device__ __align__(16) __nv_bfloat16 g_kh[NTOK*DD];
__device__ __align__(16) __nv_bfloat16 g_kl[NTOK*DD];
__device__ __align__(16) __half        g_vf[NTOK*HH];   // [b][h][s] fp16
__device__ float g_gate[NTOK*HH];                        // [tok][h] fp32

__device__ __forceinline__ float silu_f(float x) {
    return x / (1.0f + expf(-x));
}

__device__ __forceinline__ void bsplit(float x, unsigned short& hi, unsigned short& lo) {
    __nv_bfloat16 h = __float2bfloat16(x);
    __nv_bfloat16 l = __float2bfloat16(x - __bfloat162float(h));
    hi = __bfloat16_as_ushort(h);
    lo = __bfloat16_as_ushort(l);
}

#define LDSM4(r0, r1, r2, r3, a)                                              \
    asm volatile("ldmatrix.sync.aligned.m8n8.x4.shared.b16 {%0,%1,%2,%3},[%4];" \
                 : "=r"(r0), "=r"(r1), "=r"(r2), "=r"(r3) : "r"(a));

#define MMABF16(d, a0, a1, a2, a3, b0, b1)                                    \
    asm volatile("mma.sync.aligned.m16n8k16.row.col.f32.bf16.bf16.f32 "       \
                 "{%0,%1,%2,%3},{%4,%5,%6,%7},{%8,%9},{%0,%1,%2,%3};"         \
                 : "+f"(d[0]), "+f"(d[1]), "+f"(d[2]), "+f"(d[3])             \
                 : "r"(a0), "r"(a1), "r"(a2), "r"(a3), "r"(b0), "r"(b1));

#define MMAF16(d, a0, a1, a2, a3, b0, b1)                                     \
    asm volatile("mma.sync.aligned.m16n8k16.row.col.f32.f16.f16.f32 "         \
                 "{%0,%1,%2,%3},{%4,%5,%6,%7},{%8,%9},{%0,%1,%2,%3};"         \
                 : "+f"(d[0]), "+f"(d[1]), "+f"(d[2]), "+f"(d[3])             \
                 : "r"(a0), "r"(a1), "r"(a2), "r"(a3), "r"(b0), "r"(b1));

#define CP16(dst, src) \
    asm volatile("cp.async.cg.shared.global [%0], [%1], 16;" \
                 :: "r"(dst), "l"(src) : "memory")
#define CP_COMMIT() asm volatile("cp.async.commit_group;" ::: "memory")
#define CP_WAIT(n)  asm volatile("cp.async.wait_group %0;" :: "n"(n) : "memory")

// ---------------------------------------------------------------------------
// Kernel 1: per-token preproc. rope+LN, q/k split-bf16, v fp16 transposed,
// gate fp32.
// ---------------------------------------------------------------------------
__global__ void __launch_bounds__(256) k_pre(
    const float* __restrict__ q_in, const float* __restrict__ v_in,
    const float* __restrict__ ln_g, const float* __restrict__ ln_b,
    const float* __restrict__ Wg,   const float* __restrict__ bg,
    const float* __restrict__ Wqk,  const float* __restrict__ bqk,
    const float* __restrict__ gam,  const float* __restrict__ bet)
{
    __shared__ float nrm[16][128];
    __shared__ float val[16][128];

    const int t = threadIdx.x;
    const int w = t >> 5, l = t & 31;
    const long g0 = (long)blockIdx.x * 16;

    for (int u = 0; u < 2; ++u) {
        const int tok = w * 2 + u;
        const long g = g0 + tok;
        const int s = (int)(g & (SS - 1));

        float4 x = reinterpret_cast<const float4*>(q_in)[g * 32 + l];

        if (l < 8) {
            const float f0 = powf(10000.0f, -(float)(4 * l)     / 32.0f);
            const float f1 = powf(10000.0f, -(float)(4 * l + 2) / 32.0f);
            float s0, c0, s1, c1;
            sincosf((float)s * f0, &s0, &c0);
            sincosf((float)s * f1, &s1, &c1);
            float a = x.x, b2 = x.y;
            x.x = a * c0 - b2 * s0;  x.y = b2 * c0 + a * s0;
            a = x.z;  b2 = x.w;
            x.z = a * c1 - b2 * s1;  x.w = b2 * c1 + a * s1;
        }

        float sum = x.x + x.y + x.z + x.w;
        float sq  = x.x*x.x + x.y*x.y + x.z*x.z + x.w*x.w;
        #pragma unroll
        for (int o = 16; o > 0; o >>= 1) {
            sum += __shfl_xor_sync(0xffffffffu, sum, o);
            sq  += __shfl_xor_sync(0xffffffffu, sq,  o);
        }
        const float mu  = sum * (1.0f / 128.0f);
        const float var = sq  * (1.0f / 128.0f) - mu * mu;
        const float rs  = rsqrtf(var + 1e-5f);

        const int d0 = 4 * l;
        float4 n;
        n.x = (x.x - mu) * rs * ln_g[d0 + 0] + ln_b[d0 + 0];
        n.y = (x.y - mu) * rs * ln_g[d0 + 1] + ln_b[d0 + 1];
        n.z = (x.z - mu) * rs * ln_g[d0 + 2] + ln_b[d0 + 2];
        n.w = (x.w - mu) * rs * ln_g[d0 + 3] + ln_b[d0 + 3];
        reinterpret_cast<float4*>(&nrm[tok][0])[l] = n;
        reinterpret_cast<float4*>(&val[tok][0])[l] =
            reinterpret_cast<const float4*>(v_in)[g * 32 + l];
    }
    __syncthreads();

    {   // qk -> q,k (split bf16)
        const int c = t & 127, half = t >> 7;
        float acc[8];
        #pragma unroll
        for (int j = 0; j < 8; ++j) acc[j] = 0.0f;
        for (int k = 0; k < 128; ++k) {
            const float wv = Wqk[k * 128 + c];
            #pragma unroll
            for (int j = 0; j < 8; ++j)
                acc[j] += nrm[2 * j + half][k] * wv;
        }
        const float gz0 = gam[c], gz1 = gam[128 + c];
        const float bz0 = bet[c], bz1 = bet[128 + c];
        const float bb = bqk[c];
        #pragma unroll
        for (int j = 0; j < 8; ++j) {
            const long g = g0 + 2 * j + half;
            const float sl = silu_f(acc[j] + bb);
            const float qv = sl * gz0 + bz0;
            const float kv = sl * gz1 + bz1;
            unsigned short hi, lo;
            bsplit(qv, hi, lo);
            g_qh[g * 128 + c] = __ushort_as_bfloat16(hi);
            g_ql[g * 128 + c] = __ushort_as_bfloat16(lo);
            bsplit(kv, hi, lo);
            g_kh[g * 128 + c] = __ushort_as_bfloat16(hi);
            g_kl[g * 128 + c] = __ushort_as_bfloat16(lo);
        }
    }

    {   // gate (fp32), v (fp16, transposed [b][h][s])
        const int c = t;
        const int bidx = (int)(g0 >> 12);
        const int s0   = (int)(g0 & (SS - 1));
        float ag[16], av[16];
        #pragma unroll
        for (int j = 0; j < 16; ++j) { ag[j] = 0.0f; av[j] = 0.0f; }
        for (int k = 0; k < 128; ++k) {
            const float wv = Wg[k * 256 + c];
            #pragma unroll
            for (int j = 0; j < 16; ++j) {
                ag[j] += nrm[j][k] * wv;
                av[j] += val[j][k] * wv;
            }
        }
        const float bb = bg[c];
        #pragma unroll
        for (int j = 0; j < 16; ++j) {
            const long g = g0 + j;
            g_gate[g * 256 + c] = silu_f(ag[j] + bb);
            const float vv = silu_f(av[j] + bb);
            g_vf[((size_t)bidx * HH + c) * SS + s0 + j] = __float2half_rn(vv);
        }
    }
}

// ---------------------------------------------------------------------------
// Kernel 2: HMMA attention. 128 q-rows/CTA, 512 threads, 16 warps.
// sim: bf16 3-MMA split (att_map precision). PV: fp16 single-pass, attn
// pre-scaled by 2^30 (descale in epilogue).
// k double-buffered (cp.async spans whole tile); v single (spans sim phase).
// smem ushort units, strides 136 / 72 (conflict-free LDSM).
// ---------------------------------------------------------------------------
#define QS_H 0
#define QS_L (128*136)
#define KS0_H (2*128*136)
#define KS0_L (KS0_H + 64*136)
#define KS1_H (KS0_L + 64*136)
#define KS1_L (KS1_H + 64*136)
#define VS    (KS1_L + 64*136)
#define AS    (VS + 256*72)
#define SM_HALVES (AS + 128*72)
#define SMEM_BYTES (SM_HALVES*2)   // 194,560 B
#define OGS 264

__global__ void __launch_bounds__(512, 1) k_attn(
    const float* __restrict__ Wout, const float* __restrict__ bout,
    float* __restrict__ out, float* __restrict__ att)
{
    extern __shared__ __align__(16) unsigned short sb[];

    const int t = threadIdx.x, w = t >> 5, l = t & 31;
    const int b = blockIdx.y, i0 = blockIdx.x * 128;
    const long tbase = (long)b * SS;
    const int wm = w & 7, wh = w >> 3;          // sim mapping
    const int rm = wm * 16, cn = wh * 32;
    const int wr = w & 3, wc = w >> 2;          // PV mapping
    const int pr = wr * 32, ph = wc * 64;

    const int l15 = l & 15;
    const int lh  = (l >> 4) << 3;
    const int grp = l >> 3;
    const int brow2 = ((grp >> 1) << 3) + (l & 7);
    const int bcol2 = (grp & 1) << 3;

    const uint32_t sbase = (uint32_t)__cvta_generic_to_shared(sb);

    const uint4* gq4h = (const uint4*)g_qh;
    const uint4* gq4l = (const uint4*)g_ql;
    const uint4* gk4h = (const uint4*)g_kh;
    const uint4* gk4l = (const uint4*)g_kl;
    const uint4* gv4  = (const uint4*)g_vf;

    // cp.async lane assignments
    const int kr = t >> 3, kc = (t & 7) * 2;     // k: 64 rows x 16 uint4
    const int vh = t >> 1, vc = (t & 1) * 4;     // v: 256 rows x 8 uint4

    // ---- prologue: prefetch k(0) into buf0; load q tile ----
    {
        CP16(sbase + 2u*KS0_H + (uint32_t)(kr*17 + kc    )*16,
             (const void*)&gk4h[(tbase + kr) * 16 + kc]);
        CP16(sbase + 2u*KS0_H + (uint32_t)(kr*17 + kc + 1)*16,
             (const void*)&gk4h[(tbase + kr) * 16 + kc + 1]);
        CP16(sbase + 2u*KS0_L + (uint32_t)(kr*17 + kc    )*16,
             (const void*)&gk4l[(tbase + kr) * 16 + kc]);
        CP16(sbase + 2u*KS0_L + (uint32_t)(kr*17 + kc + 1)*16,
             (const void*)&gk4l[(tbase + kr) * 16 + kc + 1]);
        CP_COMMIT();
    }
    for (int i = t; i < 128 * 16; i += 512) {
        const int r = i >> 4, c4 = i & 15;
        ((uint4*)(sb + QS_H))[r * 17 + c4] = gq4h[(tbase + i0 + r) * 16 + c4];
        ((uint4*)(sb + QS_L))[r * 17 + c4] = gq4l[(tbase + i0 + r) * 16 + c4];
    }

    float o[2][8][4];
    #pragma unroll
    for (int a = 0; a < 2; ++a)
        #pragma unroll
        for (int j = 0; j < 8; ++j)
            #pragma unroll
            for (int c = 0; c < 4; ++c) o[a][j][c] = 0.0f;

    float2* attb2 = (float2*)(att + (size_t)b * SS * SS);
    const float invS = 1.0f / (float)SS;

    for (int it = 0; it < NT; ++it) {
        const int j0 = it * 64;
        const uint32_t ksh = (it & 1) ? KS1_H : KS0_H;
        const uint32_t ksl = (it & 1) ? KS1_L : KS0_L;

        CP_WAIT(0);          // k(it) resident
        __syncthreads();     // k visible; PV(it-1) readers of v/as done

        // prefetch v(it): overlaps sim + convert   [group G1]
        {
            const size_t src = ((size_t)b * HH + vh) * (SS / 8) + (j0 >> 3) + vc;
            #pragma unroll
            for (int u = 0; u < 4; ++u)
                CP16(sbase + 2u*VS + (uint32_t)(vh*9 + vc + u)*16,
                     (const void*)&gv4[src + u]);
            CP_COMMIT();
        }
        // prefetch k(it+1) into other buffer: overlaps whole tile [group G2]
        if (it + 1 < NT) {
            const uint32_t nh = (it & 1) ? KS0_H : KS1_H;
            const uint32_t nl = (it & 1) ? KS0_L : KS1_L;
            CP16(sbase + 2u*nh + (uint32_t)(kr*17 + kc    )*16,
                 (const void*)&gk4h[(tbase + j0 + 64 + kr) * 16 + kc]);
            CP16(sbase + 2u*nh + (uint32_t)(kr*17 + kc + 1)*16,
                 (const void*)&gk4h[(tbase + j0 + 64 + kr) * 16 + kc + 1]);
            CP16(sbase + 2u*nl + (uint32_t)(kr*17 + kc    )*16,
                 (const void*)&gk4l[(tbase + j0 + 64 + kr) * 16 + kc]);
            CP16(sbase + 2u*nl + (uint32_t)(kr*17 + kc + 1)*16,
                 (const void*)&gk4l[(tbase + j0 + 64 + kr) * 16 + kc + 1]);
            CP_COMMIT();
        }

        // ---- sim: rows rm..+15, cols cn..+31, bf16 3-MMA split ----
        float s[4][4];
        #pragma unroll
        for (int i = 0; i < 4; ++i)
            #pragma unroll
            for (int j = 0; j < 4; ++j) s[i][j] = 0.0f;

        #pragma unroll
        for (int kk = 0; kk < 8; ++kk) {
            const int k0 = kk * 16;
            uint32_t ah0, ah1, ah2, ah3, al0, al1, al2, al3, bh[8], bl[8];
            LDSM4(ah0, ah1, ah2, ah3, sbase + 2u*(QS_H + (rm + l15)*136 + k0 + lh));
            LDSM4(al0, al1, al2, al3, sbase + 2u*(QS_L + (rm + l15)*136 + k0 + lh));
            LDSM4(bh[0], bh[1], bh[2], bh[3],
                  sbase + 2u*(ksh + (cn + brow2)*136 + k0 + bcol2));
            LDSM4(bh[4], bh[5], bh[6], bh[7],
                  sbase + 2u*(ksh + (cn + 16 + brow2)*136 + k0 + bcol2));
            LDSM4(bl[0], bl[1], bl[2], bl[3],
                  sbase + 2u*(ksl + (cn + brow2)*136 + k0 + bcol2));
            LDSM4(bl[4], bl[5], bl[6], bl[7],
                  sbase + 2u*(ksl + (cn + 16 + brow2)*136 + k0 + bcol2));
            #pragma unroll
            for (int nt = 0; nt < 4; ++nt)
                MMABF16(s[nt], ah0, ah1, ah2, ah3, bh[2*nt], bh[2*nt+1]);
            #pragma unroll
            for (int nt = 0; nt < 4; ++nt)
                MMABF16(s[nt], al0, al1, al2, al3, bh[2*nt], bh[2*nt+1]);
            #pragma unroll
            for (int nt = 0; nt < 4; ++nt)
                MMABF16(s[nt], ah0, ah1, ah2, ah3, bl[2*nt], bl[2*nt+1]);
        }

        // ---- relu^2/S^2 -> att (fp32 global) + as (fp16 * 2^30, smem) ----
        {
            const int ra = rm + (l >> 2);
            const int rb = ra + 8;
            #pragma unroll
            for (int nt = 0; nt < 4; ++nt) {
                const int colg = cn + nt * 8 + 2 * (l & 3);
                float x;
                x = fmaxf(s[nt][0], 0.0f) * invS; const float a0 = x * x;
                x = fmaxf(s[nt][1], 0.0f) * invS; const float a1 = x * x;
                x = fmaxf(s[nt][2], 0.0f) * invS; const float a2 = x * x;
                x = fmaxf(s[nt][3], 0.0f) * invS; const float a3 = x * x;

                attb2[((size_t)(i0 + ra) * SS + j0 + colg) >> 1] = make_float2(a0, a1);
                attb2[((size_t)(i0 + rb) * SS + j0 + colg) >> 1] = make_float2(a2, a3);

                const unsigned short f0 = __half_as_ushort(__float2half_rn(a0 * ASCALE));
                const unsigned short f1 = __half_as_ushort(__float2half_rn(a1 * ASCALE));
                const unsigned short f2 = __half_as_ushort(__float2half_rn(a2 * ASCALE));
                const unsigned short f3 = __half_as_ushort(__float2half_rn(a3 * ASCALE));
                *(uint32_t*)(sb + AS + ra * 72 + colg) = (uint32_t)f0 | ((uint32_t)f1 << 16);
                *(uint32_t*)(sb + AS + rb * 72 + colg) = (uint32_t)f2 | ((uint32_t)f3 << 16);
            }
        }

        if (it + 1 < NT) { CP_WAIT(1); } else { CP_WAIT(0); }  // v(it) done
        __syncthreads();     // as + v visible everywhere

        // ---- PV (fp16 single): rows pr..+31, h ph..+63 ----
        #pragma unroll
        for (int kt = 0; kt < 4; ++kt) {
            const int tok0 = kt * 16;
            uint32_t A0[4], A1[4], Bv[16];
            LDSM4(A0[0], A0[1], A0[2], A0[3],
                  sbase + 2u*(AS + (pr + l15)*72 + tok0 + lh));
            LDSM4(A1[0], A1[1], A1[2], A1[3],
                  sbase + 2u*(AS + (pr + 16 + l15)*72 + tok0 + lh));
            #pragma unroll
            for (int hp = 0; hp < 4; ++hp)
                LDSM4(Bv[4*hp], Bv[4*hp+1], Bv[4*hp+2], Bv[4*hp+3],
                      sbase + 2u*(VS + (ph + hp*16 + brow2)*72 + tok0 + bcol2));
            #pragma unroll
            for (int j = 0; j < 8; ++j)
                MMAF16(o[0][j], A0[0], A0[1], A0[2], A0[3], Bv[2*j], Bv[2*j+1]);
            #pragma unroll
            for (int j = 0; j < 8; ++j)
                MMAF16(o[1][j], A1[0], A1[1], A1[2], A1[3], Bv[2*j], Bv[2*j+1]);
        }
    }

    // ---- epilogue: og = o * gate * 2^-30 -> smem, then @ W_out + b ----
    __syncthreads();
    float* og = (float*)sb;
    {
        const int ra0 = pr + (l >> 2);
        #pragma unroll
        for (int rg = 0; rg < 2; ++rg) {
            const int ra = ra0 + rg * 16;
            const int rb = ra + 8;
            #pragma unroll
            for (int j = 0; j < 8; ++j) {
                const int hc = ph + (j >> 1) * 16 + (j & 1) * 8 + 2 * (l & 3);
                const float2 ga = *(const float2*)&g_gate[(tbase + i0 + ra) * 256 + hc];
                const float2 gb = *(const float2*)&g_gate[(tbase + i0 + rb) * 256 + hc];
                *(float2*)&og[ra * OGS + hc] =
                    make_float2(o[rg][j][0] * ga.x * INV_ASCALE,
                                o[rg][j][1] * ga.y * INV_ASCALE);
                *(float2*)&og[rb * OGS + hc] =
                    make_float2(o[rg][j][2] * gb.x * INV_ASCALE,
                                o[rg][j][3] * gb.y * INV_ASCALE);
            }
        }
    }
    __syncthreads();

    {
        const int c = t & 127, r0 = t >> 7;
        float acc2[32];
        #pragma unroll
        for (int i = 0; i < 32; ++i) acc2[i] = 0.0f;
        for (int h = 0; h < 256; ++h) {
            const float wv = Wout[h * 128 + c];
            #pragma unroll
            for (int i = 0; i < 32; ++i)
                acc2[i] += og[(r0 + 4 * i) * OGS + h] * wv;  // smem broadcast
        }
        const float bb = bout[c];
        #pragma unroll
        for (int i = 0; i < 32; ++i)
            out[(tbase + i0 + r0 + 4 * i) * 128 + c] = acc2[i] + bb;
    }
}

// ---------------------------------------------------------------------------
extern "C" void kernel_launch(void* const* d_in, const int* in_sizes, int n_in,
                              void* d_out, int out_size)
{
    const float* query = (const float*)d_in[0];
    const float* value = (const float*)d_in[2];
    const float* ln_g  = (const float*)d_in[3];
    const float* ln_b  = (const float*)d_in[4];
    const float* Wg    = (const float*)d_in[5];
    const float* bg    = (const float*)d_in[6];
    const float* Wqk   = (const float*)d_in[7];
    const float* bqk   = (const float*)d_in[8];
    const float* gam   = (const float*)d_in[9];
    const float* bet   = (const float*)d_in[10];
    const float* Wout  = (const float*)d_in[11];
    const float* bout  = (const float*)d_in[12];

    float* out = (float*)d_out;                       // [B,S,D] first
    float* att = out + (size_t)BB * SS * DD;          // then [B,S,S]

    cudaFuncSetAttribute(k_attn, cudaFuncAttributeMaxDynamicSharedMemorySize,
                         SMEM_BYTES);

    k_pre<<<NTOK / 16, 256>>>(query, value, ln_g, ln_b, Wg, bg, Wqk, bqk, gam, bet);

    dim3 g2(SS / 128, BB);
    k_attn<<<g2, 512, SMEM_BYTES>>>(Wout, bout, out, att);
}